// round 9
// baseline (speedup 1.0000x reference)
#include <cuda_runtime.h>
#include <math.h>

#define NP 8732
#define NG 16
#define NC 21
#define NTILES 273
#define SPLIT 3
#define STILES 91          // 273 = 3 * 91
#define TPB 512
#define WPB 16
#define MAXB 128

__device__ unsigned long long g_best[MAXB * NG];
__device__ float g_sll[MAXB * SPLIT];
__device__ float g_slc[MAXB * SPLIT];
__device__ int   g_snp[MAXB * SPLIT];
__device__ float g_lcb[MAXB * NP];
__device__ unsigned char g_gpb[MAXB * NP];
__device__ float g_bll[MAXB];
__device__ float g_blc[MAXB];
__device__ int   g_bnp[MAXB];
__device__ unsigned g_arrive = 0;

// smooth-L1 loc loss; single implementation for bit-identical math everywhere
__device__ __forceinline__ float sl1_calc(const float* __restrict__ ld,
                                          float4 pr, const float* t) {
    float vx = 0.1f * pr.z;
    float vy = 0.1f * pr.w;
    float lts[10];
    lts[0] = ((t[0] + t[2]) * 0.5f - pr.x) / vx;
    lts[1] = ((t[1] + t[3]) * 0.5f - pr.y) / vy;
    lts[2] = logf((t[2] - t[0]) / pr.z) / 0.2f;
    lts[3] = logf((t[3] - t[1]) / pr.w) / 0.2f;
    lts[4] = logf(t[4] / pr.z + 0.1f) / 0.2f;
    lts[5] = logf(t[5] / pr.w + 0.1f) / 0.2f;
    lts[6] = logf(t[6] / pr.z + 0.1f) / 0.2f;
    lts[7] = logf(t[7] / pr.w + 0.1f) / 0.2f;
    lts[8] = (t[8] - pr.x) / vx;
    lts[9] = (t[9] - pr.y) / vy;
    float ll = 0.0f;
#pragma unroll
    for (int j = 0; j < 10; j++) {
        float d  = __ldg(ld + j) - lts[j];
        float ad = fabsf(d);
        ll += (ad < 1.0f) ? (0.5f * d) * d : (ad - 0.5f);
    }
    return ll;
}

struct __align__(16) SmemA {
    float stage[WPB * 672];
    float tg[NG * 11];
    float4 box[NG];
    float taa[NG];
    unsigned long long sbest[NG];
    unsigned char sgp[STILES * 32 + 4];
    float rf[WPB];
    float rf2[WPB];
    int   ri[WPB];
};

__global__ void __launch_bounds__(TPB, 3) mb_pass(
    const float* __restrict__ loc_data,   // [B, NP, 10]
    const float* __restrict__ conf_data,  // [B, NP, 21]
    const float* __restrict__ priors,     // [NP, 4]
    const float* __restrict__ targets)    // [B, NG, 11]
{
    extern __shared__ char smem_raw[];
    SmemA* S = (SmemA*)smem_raw;

    const int b    = blockIdx.x / SPLIT;
    const int sl   = blockIdx.x % SPLIT;
    const int tid  = threadIdx.x;
    const int lane = tid & 31;
    const int wrp  = tid >> 5;
    const int T0   = sl * STILES;
    const int P0   = T0 * 32;
    const int P1   = (NP < P0 + STILES * 32) ? NP : (P0 + STILES * 32);

    for (int i = tid; i < NG * 11; i += TPB)
        S->tg[i] = targets[b * NG * 11 + i];
    if (tid < NG) S->sbest[tid] = 0ull;
    __syncthreads();
    if (tid < NG) {
        const float* t = S->tg + tid * 11;
        float4 bx = make_float4(t[0], t[1], t[2], t[3]);
        S->box[tid] = bx;
        S->taa[tid] = (bx.z - bx.x) * (bx.w - bx.y);
    }
    __syncthreads();

    // ---- pass 1: matching over this slice (fast-quotient decisions) ----
#pragma unroll 1
    for (int p = P0 + tid; p < P1; p += TPB) {
        float4 pr = __ldg((const float4*)priors + p);
        float pax = pr.x - 0.5f * pr.z;
        float pay = pr.y - 0.5f * pr.w;
        float pbx = pr.x + 0.5f * pr.z;
        float pby = pr.y + 0.5f * pr.w;
        float pare = (pbx - pax) * (pby - pay);
        float bq = -1.0f;
        int bg = 0;
#pragma unroll
        for (int g = 0; g < NG; g++) {
            float4 t = S->box[g];
            float ix = fminf(t.z, pbx) - fmaxf(t.x, pax);
            float iy = fminf(t.w, pby) - fmaxf(t.y, pay);
            ix = fmaxf(ix, 0.0f);
            iy = fmaxf(iy, 0.0f);
            float inter = ix * iy;
            float den = (S->taa[g] + pare) - inter;   // > 0
            float q = __fdividef(inter, den);
            if (q > bq) { bq = q; bg = g; }           // strict > : first max over g
            // per-gt argmax: pack (q, smaller-p-wins) into u64, smem atomicMax
            unsigned long long pk =
                ((unsigned long long)__float_as_uint(q) << 32) |
                (unsigned)(0x7fffffff - p);
            unsigned long long cur = *(volatile unsigned long long*)&S->sbest[g];
            if (pk > cur) atomicMax(&S->sbest[g], pk);
        }
        unsigned char v = (unsigned char)bg | ((bq >= 0.5f) ? 0x10 : 0x00);
        S->sgp[p - P0] = v;
        g_gpb[b * NP + p] = v;
    }
    __syncthreads();
    if (tid < NG) atomicMax(&g_best[b * NG + tid], S->sbest[tid]);

    // ---- pass 2: per-prior losses over this slice ----
    float ll = 0.0f, lcp = 0.0f;
    int   np = 0;
    float* stg = S->stage + wrp * 672;
    float4* stg4 = (float4*)stg;
    const float* confb = conf_data + (size_t)b * NP * NC;

#pragma unroll 1
    for (int tile = T0 + wrp; tile < T0 + STILES; tile += WPB) {
        const int p0 = tile * 32;
        const int cnt = (NP - p0 < 32) ? (NP - p0) : 32;
        const int tcnt4 = (cnt * NC) >> 2;
        const float4* cb4 = (const float4*)(confb + (size_t)p0 * NC);
#pragma unroll
        for (int j = 0; j < 6; j++) {
            int idx2 = j * 32 + lane;
            if (idx2 < tcnt4) stg4[idx2] = __ldg(cb4 + idx2);
        }
        __syncwarp();

        const int p = p0 + lane;
        if (p < NP) {
            unsigned gpv = S->sgp[p - P0];
            int gi = gpv & 15;
            bool pos = (gpv & 0x10) != 0;
            int conf = pos ? ((int)S->tg[gi * 11 + 10] + 1) : 0;

            const float* row = stg + lane * NC;
            float s = 0.0f;
#pragma unroll
            for (int j = 0; j < NC; j++) s += __expf(row[j]);
            float lca = __logf(s) - row[conf];

            float lc = lca;
            if (pos) {
                lc = 0.0f;
                np++;
                lcp += lca;
                float4 pr = __ldg((const float4*)priors + p);
                ll += sl1_calc(loc_data + ((size_t)b * NP + p) * 10, pr,
                               S->tg + gi * 11);
            }
            g_lcb[b * NP + p] = lc;
        }
        __syncwarp();
    }

    // ---- block reduce (16 warps) -> per-slice partials ----
#pragma unroll
    for (int o = 16; o > 0; o >>= 1) {
        ll  += __shfl_down_sync(0xffffffffu, ll, o);
        lcp += __shfl_down_sync(0xffffffffu, lcp, o);
        np  += __shfl_down_sync(0xffffffffu, np, o);
    }
    if (lane == 0) { S->rf[wrp] = ll; S->rf2[wrp] = lcp; S->ri[wrp] = np; }
    __syncthreads();
    if (tid < 32) {
        float ll_t = (tid < WPB) ? S->rf[tid] : 0.0f;
        float lcp_t = (tid < WPB) ? S->rf2[tid] : 0.0f;
        int   np_t = (tid < WPB) ? S->ri[tid] : 0;
#pragma unroll
        for (int o = 8; o > 0; o >>= 1) {
            ll_t  += __shfl_down_sync(0xffffffffu, ll_t, o);
            lcp_t += __shfl_down_sync(0xffffffffu, lcp_t, o);
            np_t  += __shfl_down_sync(0xffffffffu, np_t, o);
        }
        if (tid == 0) {
            g_sll[blockIdx.x] = ll_t;
            g_slc[blockIdx.x] = lcp_t;
            g_snp[blockIdx.x] = np_t;
        }
    }
}

struct __align__(16) SmemB {
    float slc[NP];
    unsigned hist[2048];
    float tg[NG * 11];
    int   bp[NG];
    float dll[NG];
    float dlc[NG];
    int   dnp[NG];
    float rf[WPB];
    float rf2[WPB];
    int   ri[WPB];
    unsigned gsum[WPB];
    int   bc[4];
};

__global__ void __launch_bounds__(TPB) mb_final(
    const float* __restrict__ loc_data,
    const float* __restrict__ conf_data,
    const float* __restrict__ priors,
    const float* __restrict__ targets,
    float* __restrict__ out, int B)
{
    extern __shared__ char smem_raw[];
    SmemB* S = (SmemB*)smem_raw;
    unsigned* hist = S->hist;

    const int b    = blockIdx.x;
    const int tid  = threadIdx.x;
    const int lane = tid & 31;
    const int wrp  = tid >> 5;

    for (int i = tid; i < NG * 11; i += TPB)
        S->tg[i] = targets[b * NG * 11 + i];
    for (int i = tid; i < NP; i += TPB)
        S->slc[i] = g_lcb[b * NP + i];
    if (tid < NG)
        S->bp[tid] = 0x7fffffff - (int)(unsigned)(g_best[b * NG + tid] & 0xffffffffull);
    __syncthreads();

    // ---- corrections for overridden priors (<=16), exact semantics ----
    if (tid < NG) {
        const int j = tid;
        const int p = S->bp[j];
        bool last = true;
#pragma unroll
        for (int j2 = j + 1; j2 < NG; j2++)
            if (S->bp[j2] == p) last = false;
        float dll = 0.0f, dlc = 0.0f;
        int dnp = 0;
        if (last) {
            unsigned old = g_gpb[b * NP + p];
            int gio = old & 15;
            bool poso = (old & 0x10) != 0;
            if (!(poso && gio == j)) {
                const float* c = conf_data + ((size_t)b * NP + p) * NC;
                float s = 0.0f;
#pragma unroll
                for (int j2 = 0; j2 < NC; j2++) s += __expf(__ldg(c + j2));
                float lse = __logf(s);
                const float* tn = S->tg + j * 11;
                int cn = (int)tn[10] + 1;
                float4 pr2 = __ldg((const float4*)priors + p);
                const float* ld = loc_data + ((size_t)b * NP + p) * 10;
                dlc = lse - __ldg(c + cn);
                dll = sl1_calc(ld, pr2, tn);
                dnp = poso ? 0 : 1;
                if (poso) {
                    const float* to = S->tg + gio * 11;
                    int co = (int)to[10] + 1;
                    dlc -= (lse - __ldg(c + co));
                    dll -= sl1_calc(ld, pr2, to);
                }
            }
            S->slc[p] = 0.0f;
        }
        S->dll[j] = dll;
        S->dlc[j] = dlc;
        S->dnp[j] = dnp;
    }
    __syncthreads();
    if (tid == 0) {
        float ll_t = 0.0f, lcp_t = 0.0f;
        int   np_t = 0;
#pragma unroll
        for (int s2 = 0; s2 < SPLIT; s2++) {
            ll_t  += g_sll[b * SPLIT + s2];
            lcp_t += g_slc[b * SPLIT + s2];
            np_t  += g_snp[b * SPLIT + s2];
        }
#pragma unroll
        for (int j = 0; j < NG; j++) {
            ll_t  += S->dll[j];
            lcp_t += S->dlc[j];
            np_t  += S->dnp[j];
        }
        S->rf[0] = ll_t; S->rf2[0] = lcp_t; S->bc[0] = np_t;
    }
    __syncthreads();
    const int np_tot = S->bc[0];
    const float ll_tot = S->rf[0];
    const float lcp_tot = S->rf2[0];
    int k = 3 * np_tot;
    if (k > NP - 1) k = NP - 1;

    // ---- exact top-k sum via 3-round radix select (512 threads) ----
    float Ssum = 0.0f;
    if (k > 0) {
        unsigned prefix = 0u, pmask = 0u;
        const int shifts[3] = {21, 10, 0};
        const int rbits[3]  = {11, 11, 10};
        int kk = k;
        for (int r = 0; r < 3; r++) {
            for (int i = tid; i < 2048; i += TPB) hist[i] = 0u;
            __syncthreads();
            const unsigned nb = 1u << rbits[r];
#pragma unroll 1
            for (int p = tid; p < 9216; p += TPB) {
                bool valid = p < NP;
                unsigned bb = valid ? __float_as_uint(S->slc[p]) : 0u;
                bool sel = valid && ((bb & pmask) == prefix);
                unsigned bin = sel ? ((bb >> shifts[r]) & (nb - 1u)) : 0xffffffffu;
                unsigned grp = __match_any_sync(0xffffffffu, bin);
                if (sel && lane == (__ffs(grp) - 1))
                    atomicAdd(&hist[bin], (unsigned)__popc(grp));
            }
            __syncthreads();
            unsigned c0 = hist[tid * 4 + 0], c1 = hist[tid * 4 + 1];
            unsigned c2 = hist[tid * 4 + 2], c3 = hist[tid * 4 + 3];
            unsigned sloc = c0 + c1 + c2 + c3;
            unsigned suf = sloc;
#pragma unroll
            for (int o = 1; o < 32; o <<= 1) {
                unsigned v = __shfl_down_sync(0xffffffffu, suf, o);
                if (lane + o < 32) suf += v;
            }
            if (lane == 0) S->gsum[wrp] = suf;
            __syncthreads();
            unsigned above = 0;
            for (int w = wrp + 1; w < WPB; w++) above += S->gsum[w];
            unsigned excl3 = above + (suf - sloc);
            unsigned excl2 = excl3 + c3;
            unsigned excl1 = excl2 + c2;
            unsigned excl0 = excl1 + c1;
            unsigned ukk = (unsigned)kk;
            if (excl3 < ukk && ukk <= excl3 + c3) { S->bc[1] = tid * 4 + 3; S->bc[2] = (int)(ukk - excl3); }
            if (excl2 < ukk && ukk <= excl2 + c2) { S->bc[1] = tid * 4 + 2; S->bc[2] = (int)(ukk - excl2); }
            if (excl1 < ukk && ukk <= excl1 + c1) { S->bc[1] = tid * 4 + 1; S->bc[2] = (int)(ukk - excl1); }
            if (excl0 < ukk && ukk <= excl0 + c0) { S->bc[1] = tid * 4 + 0; S->bc[2] = (int)(ukk - excl0); }
            __syncthreads();
            int chosen = S->bc[1];
            kk = S->bc[2];
            prefix |= ((unsigned)chosen) << shifts[r];
            pmask  |= ((1u << rbits[r]) - 1u) << shifts[r];
            __syncthreads();
        }
        const float tv = __uint_as_float(prefix);
        float sgt = 0.0f;
        int   cgt = 0;
#pragma unroll 1
        for (int p = tid; p < NP; p += TPB) {
            float v = S->slc[p];
            if (__float_as_uint(v) > prefix) { sgt += v; cgt++; }
        }
#pragma unroll
        for (int o = 16; o > 0; o >>= 1) {
            sgt += __shfl_down_sync(0xffffffffu, sgt, o);
            cgt += __shfl_down_sync(0xffffffffu, cgt, o);
        }
        if (lane == 0) { S->rf[wrp] = sgt; S->ri[wrp] = cgt; }
        __syncthreads();
        if (tid == 0) {
            float sgt_t = 0.0f;
            int   cgt_t = 0;
            for (int w = 0; w < WPB; w++) { sgt_t += S->rf[w]; cgt_t += S->ri[w]; }
            Ssum = sgt_t + (float)(k - cgt_t) * tv;
        }
    }

    // ---- publish, reset for next graph replay, last CTA finalizes ----
    if (tid < NG) g_best[b * NG + tid] = 0ull;   // consumed above; reset for next launch
    __shared__ bool slast;
    if (tid == 0) {
        g_bll[b] = ll_tot;
        g_blc[b] = lcp_tot + Ssum;
        g_bnp[b] = np_tot;
        __threadfence();
        unsigned t = atomicAdd(&g_arrive, 1u);
        slast = (t == gridDim.x - 1);
        if (slast) g_arrive = 0u;
    }
    __syncthreads();
    if (slast) {
        float fll = 0.0f, flc = 0.0f;
        int   fnp = 0;
        for (int i = tid; i < B; i += TPB) {
            fll += g_bll[i]; flc += g_blc[i]; fnp += g_bnp[i];
        }
#pragma unroll
        for (int o = 16; o > 0; o >>= 1) {
            fll += __shfl_down_sync(0xffffffffu, fll, o);
            flc += __shfl_down_sync(0xffffffffu, flc, o);
            fnp += __shfl_down_sync(0xffffffffu, fnp, o);
        }
        if (lane == 0) { S->rf[wrp] = fll; S->rf2[wrp] = flc; S->ri[wrp] = fnp; }
        __syncthreads();
        if (tid == 0) {
            float tll = 0.0f, tlc = 0.0f;
            int tnp = 0;
            for (int w = 0; w < WPB; w++) { tll += S->rf[w]; tlc += S->rf2[w]; tnp += S->ri[w]; }
            float N = (float)tnp;
            out[0] = tll / N;
            out[1] = tlc / N;
        }
    }
}

extern "C" void kernel_launch(void* const* d_in, const int* in_sizes, int n_in,
                              void* d_out, int out_size) {
    const float* loc     = (const float*)d_in[0];
    const float* conf    = (const float*)d_in[1];
    const float* priors  = (const float*)d_in[2];
    const float* targets = (const float*)d_in[3];
    const int B = in_sizes[0] / (NP * 10);

    cudaFuncSetAttribute(mb_pass, cudaFuncAttributeMaxDynamicSharedMemorySize,
                         (int)sizeof(SmemA));
    cudaFuncSetAttribute(mb_final, cudaFuncAttributeMaxDynamicSharedMemorySize,
                         (int)sizeof(SmemB));
    mb_pass<<<B * SPLIT, TPB, sizeof(SmemA)>>>(loc, conf, priors, targets);
    mb_final<<<B, TPB, sizeof(SmemB)>>>(loc, conf, priors, targets,
                                        (float*)d_out, B);
}